// round 4
// baseline (speedup 1.0000x reference)
#include <cuda_runtime.h>
#include <math.h>

// Problem constants (fixed by the reference)
#define NVAR 4000000
#define KFAC 2000000
#define DV 3
#define DC 6
#define EDGES (NVAR * DV)   // 12,000,000

// Single edge-message scratch buffer, variable-side edge order. 48MB.
// K1 writes Hsx; K2 updates IN PLACE (each slot gathered by exactly one
// factor thread which reads before writing -> race-free, deterministic);
// K3 reads contiguously. perm is never needed (perm[inv_perm[e]] == e).
__device__ float g_msg[EDGES];

// ---------------------------------------------------------------------------
// variable->factor message math for one variable (full inf/nan semantics)
// ---------------------------------------------------------------------------
__device__ __forceinline__ void var_msg(float prior, float h0, float h1, float h2,
                                        float& o0, float& o1, float& o2)
{
    bool i0 = isinf(h0), i1 = isinf(h1), i2 = isinf(h2);
    int sure = (int)i0 + (int)i1 + (int)i2;
    if (sure == 0) {
        float ll = (h0 + h1) + h2;
        o0 = prior + ll - h0;
        o1 = prior + ll - h1;
        o2 = prior + ll - h2;
    } else {
        float ll = (i0 ? 0.0f : h0) + (i1 ? 0.0f : h1) + (i2 ? 0.0f : h2);
        float ss = (i0 ? h0 : 0.0f) + (i1 ? h1 : 0.0f) + (i2 ? h2 : 0.0f);
        if (sure == 1) {
            float pl = prior + ll;
            o0 = i0 ? pl : ss;
            o1 = i1 ? pl : ss;
            o2 = i2 ? pl : ss;
        } else {
            float v = isnan(ss) ? 0.0f : (prior + ss);
            o0 = v; o1 = v; o2 = v;
        }
    }
}

// ---------------------------------------------------------------------------
// Kernel 1: variable -> factor. 4 variables per thread, all-float4 streams.
// ---------------------------------------------------------------------------
__global__ void __launch_bounds__(256)
var_update_kernel(const float4* __restrict__ ps,
                  const float4* __restrict__ Min,
                  const float4* __restrict__ Hxs_prev,
                  int n_vec)   // n_vars / 4
{
    int t = blockIdx.x * blockDim.x + threadIdx.x;
    if (t >= n_vec) return;

    // 4 variables: ps/Min are [N,2] -> 2 float4 each; Hxs_prev [N,3] -> 3 float4
    float4 p0 = ps[2 * t + 0], p1 = ps[2 * t + 1];
    float4 m0 = Min[2 * t + 0], m1 = Min[2 * t + 1];
    float4 ha = Hxs_prev[3 * t + 0];
    float4 hb = Hxs_prev[3 * t + 1];
    float4 hc = Hxs_prev[3 * t + 2];

    float pr0 = 0.5f * (__logf(m0.x) - __logf(m0.y)) + 0.5f * (__logf(p0.x) - __logf(p0.y));
    float pr1 = 0.5f * (__logf(m0.z) - __logf(m0.w)) + 0.5f * (__logf(p0.z) - __logf(p0.w));
    float pr2 = 0.5f * (__logf(m1.x) - __logf(m1.y)) + 0.5f * (__logf(p1.x) - __logf(p1.y));
    float pr3 = 0.5f * (__logf(m1.z) - __logf(m1.w)) + 0.5f * (__logf(p1.z) - __logf(p1.w));

    float4 oa, ob, oc;
    var_msg(pr0, ha.x, ha.y, ha.z, oa.x, oa.y, oa.z);
    var_msg(pr1, ha.w, hb.x, hb.y, oa.w, ob.x, ob.y);
    var_msg(pr2, hb.z, hb.w, hc.x, ob.z, ob.w, oc.x);
    var_msg(pr3, hc.y, hc.z, hc.w, oc.y, oc.z, oc.w);

    float4* out = (float4*)g_msg;
    out[3 * t + 0] = oa;
    out[3 * t + 1] = ob;
    out[3 * t + 2] = oc;
}

// ---------------------------------------------------------------------------
// factor math for one check: v[6] tanh'd, extrinsic atanh products, scatter.
// atanh via 0.5*log((1+y)/(1-y)): abs err ~1e-7, preserves +-inf at y=+-1.
// ---------------------------------------------------------------------------
__device__ __forceinline__ void fac_process(const float* __restrict__ v,
                                            const int*   __restrict__ idx,
                                            float sgn)
{
    float tt[DC];
    bool  z[DC];
    int   nz = 0;
    float prod = 1.0f;
#pragma unroll
    for (int k = 0; k < DC; k++) {
        tt[k] = tanhf(v[k]);
        z[k] = (tt[k] == 0.0f);
        nz += (int)z[k];
        prod *= z[k] ? 1.0f : tt[k];
    }
    float pn = sgn * prod;

    if (nz == 0) {
#pragma unroll
        for (int k = 0; k < DC; k++) {
            float y = __fdividef(pn, tt[k]);            // |y| <= 1
            float r = 0.5f * __logf(__fdividef(1.0f + y, 1.0f - y));
            __stcg(&g_msg[idx[k]], r);
        }
    } else if (nz == 1) {
        float y = pn;
        float ath = 0.5f * __logf(__fdividef(1.0f + y, 1.0f - y));
#pragma unroll
        for (int k = 0; k < DC; k++)
            __stcg(&g_msg[idx[k]], z[k] ? ath : 0.0f);
    } else {
#pragma unroll
        for (int k = 0; k < DC; k++)
            __stcg(&g_msg[idx[k]], 0.0f);
    }
}

// ---------------------------------------------------------------------------
// Kernel 2: factor -> variable, in place. 2 factors per thread.
// 12 indices via 3x int4 (streaming), 12 gathers issued back-to-back (MLP),
// gathers/scatters bypass L1 (.cg) - random 4B over 48MB never hits L1.
// ---------------------------------------------------------------------------
__global__ void __launch_bounds__(256)
fac_update_kernel(const int* __restrict__ inv_perm,
                  const int* __restrict__ x,
                  int n_half)   // n_fac / 2
{
    int t = blockIdx.x * blockDim.x + threadIdx.x;
    if (t >= n_half) return;

    const int4* ip4 = (const int4*)(inv_perm + 12 * t);   // 48B-aligned
    int4 a0 = __ldcs(ip4 + 0);
    int4 a1 = __ldcs(ip4 + 1);
    int4 a2 = __ldcs(ip4 + 2);
    int idx[12] = {a0.x, a0.y, a0.z, a0.w,
                   a1.x, a1.y, a1.z, a1.w,
                   a2.x, a2.y, a2.z, a2.w};

    float v[12];
#pragma unroll
    for (int k = 0; k < 12; k++)
        v[k] = __ldcg(&g_msg[idx[k]]);

    int2 xx = __ldcs((const int2*)(x + 2 * t));           // 8B-aligned
    float s0 = 1.0f - 2.0f * (float)xx.x;
    float s1 = 1.0f - 2.0f * (float)xx.y;

    fac_process(v,     idx,     s0);
    fac_process(v + 6, idx + 6, s1);
}

// ---------------------------------------------------------------------------
// Kernel 3: output beliefs. 4 variables per thread, all-float4 streams.
// ---------------------------------------------------------------------------
__device__ __forceinline__ float belief(float h0, float h1, float h2)
{
    float s = (h0 + h1) + h2;
    float d = tanhf(s);
    if (isnan(d)) {
        bool c0 = isinf(h0), c1 = isinf(h1), c2 = isinf(h2);
        if (c0 | c1 | c2) {
            float s2 = (c0 ? 0.0f : h0) + (c1 ? 0.0f : h1) + (c2 ? 0.0f : h2);
            d = tanhf(s2);
        }
    }
    return d;
}

__global__ void __launch_bounds__(256)
output_kernel(float4* __restrict__ Mout, int n_vec)   // n_vars / 4
{
    int t = blockIdx.x * blockDim.x + threadIdx.x;
    if (t >= n_vec) return;

    const float4* in = (const float4*)g_msg;
    float4 a = in[3 * t + 0];
    float4 b = in[3 * t + 1];
    float4 c = in[3 * t + 2];

    float d0 = belief(a.x, a.y, a.z);
    float d1 = belief(a.w, b.x, b.y);
    float d2 = belief(b.z, b.w, c.x);
    float d3 = belief(c.y, c.z, c.w);

    float4 o0, o1;
    o0.x = 0.5f + 0.5f * d0;  o0.y = 0.5f - 0.5f * d0;
    o0.z = 0.5f + 0.5f * d1;  o0.w = 0.5f - 0.5f * d1;
    o1.x = 0.5f + 0.5f * d2;  o1.y = 0.5f - 0.5f * d2;
    o1.z = 0.5f + 0.5f * d3;  o1.w = 0.5f - 0.5f * d3;
    Mout[2 * t + 0] = o0;
    Mout[2 * t + 1] = o1;
}

// ---------------------------------------------------------------------------
// Launch. Inputs: ps[N,2] f32, Min[N,2] f32, Hxs_prev[N,3] f32, x[K,1] i32,
// perm[E] i32 (unused), inv_perm[E] i32. Output: M_out[N,2] f32.
// N = 4,000,000 (divisible by 4), K = 2,000,000 (divisible by 2).
// ---------------------------------------------------------------------------
extern "C" void kernel_launch(void* const* d_in, const int* in_sizes, int n_in,
                              void* d_out, int out_size)
{
    const float4* ps       = (const float4*)d_in[0];
    const float4* Min      = (const float4*)d_in[1];
    const float4* Hxs_prev = (const float4*)d_in[2];
    const int*    x        = (const int*)d_in[3];
    const int*    inv_perm = (const int*)d_in[5];

    int n_vars = in_sizes[0] / 2;   // 4,000,000
    int n_fac  = in_sizes[3];       // 2,000,000
    int n_vec  = n_vars / 4;        // 1,000,000
    int n_half = n_fac / 2;         // 1,000,000

    const int T = 256;
    var_update_kernel<<<(n_vec + T - 1) / T, T>>>(ps, Min, Hxs_prev, n_vec);
    fac_update_kernel<<<(n_half + T - 1) / T, T>>>(inv_perm, x, n_half);
    output_kernel<<<(n_vec + T - 1) / T, T>>>((float4*)d_out, n_vec);
}

// round 5
// speedup vs baseline: 1.7168x; 1.7168x over previous
#include <cuda_runtime.h>
#include <math.h>

// Problem constants (fixed by the reference)
#define NVAR 4000000
#define KFAC 2000000
#define DV 3
#define DC 6
#define EDGES (NVAR * DV)   // 12,000,000

// Scratch buffers (static; allocation-free rule).
// g_msg:   variable->factor messages Hsx, variable-side edge order (48MB).
// g_pn_nz: per-factor aggregate {signed tanh-product pn, zero-count nz} (16MB).
__device__ float  g_msg[EDGES];
__device__ float2 g_pn_nz[KFAC];

// ---------------------------------------------------------------------------
// Kernel 1: variable -> factor update. One thread per variable (measured
// fastest form: 24.4us, 67% DRAM).
// ---------------------------------------------------------------------------
__global__ void __launch_bounds__(256)
var_update_kernel(const float2* __restrict__ ps,
                  const float2* __restrict__ Min,
                  const float*  __restrict__ Hxs_prev,
                  int n_vars)
{
    int n = blockIdx.x * blockDim.x + threadIdx.x;
    if (n >= n_vars) return;

    float2 m = Min[n];
    float2 p = ps[n];
    float prior = 0.5f * (__logf(m.x) - __logf(m.y))
                + 0.5f * (__logf(p.x) - __logf(p.y));

    float h0 = Hxs_prev[3 * n + 0];
    float h1 = Hxs_prev[3 * n + 1];
    float h2 = Hxs_prev[3 * n + 2];

    bool i0 = isinf(h0), i1 = isinf(h1), i2 = isinf(h2);
    int sure = (int)i0 + (int)i1 + (int)i2;

    float o0, o1, o2;
    if (sure == 0) {
        float ll = (h0 + h1) + h2;
        o0 = prior + ll - h0;
        o1 = prior + ll - h1;
        o2 = prior + ll - h2;
    } else {
        float ll = (i0 ? 0.0f : h0) + (i1 ? 0.0f : h1) + (i2 ? 0.0f : h2);
        float ss = (i0 ? h0 : 0.0f) + (i1 ? h1 : 0.0f) + (i2 ? h2 : 0.0f);
        if (sure == 1) {
            float pl = prior + ll;
            o0 = i0 ? pl : ss;
            o1 = i1 ? pl : ss;
            o2 = i2 ? pl : ss;
        } else {
            float v = isnan(ss) ? 0.0f : (prior + ss);
            o0 = v; o1 = v; o2 = v;
        }
    }
    g_msg[3 * n + 0] = o0;
    g_msg[3 * n + 1] = o1;
    g_msg[3 * n + 2] = o2;
}

// ---------------------------------------------------------------------------
// Kernel 2: factor aggregates. 2 factors per thread.
// 12 random 4B gathers (only random traffic), aggregate written CONTIGUOUS:
// pn = sign * prod of nonzero tanh's, nz = count of zero tanh's.
// ---------------------------------------------------------------------------
__global__ void __launch_bounds__(256)
fac_aggregate_kernel(const int* __restrict__ inv_perm,
                     const int* __restrict__ x,
                     int n_half)   // n_fac / 2
{
    int t = blockIdx.x * blockDim.x + threadIdx.x;
    if (t >= n_half) return;

    const int4* ip4 = (const int4*)(inv_perm + 12 * t);   // 48B-aligned
    int4 a0 = __ldcs(ip4 + 0);
    int4 a1 = __ldcs(ip4 + 1);
    int4 a2 = __ldcs(ip4 + 2);
    int idx[12] = {a0.x, a0.y, a0.z, a0.w,
                   a1.x, a1.y, a1.z, a1.w,
                   a2.x, a2.y, a2.z, a2.w};

    float v[12];
#pragma unroll
    for (int k = 0; k < 12; k++)
        v[k] = __ldcg(&g_msg[idx[k]]);

    int2 xx = __ldcs((const int2*)(x + 2 * t));
    float sgn0 = 1.0f - 2.0f * (float)xx.x;
    float sgn1 = 1.0f - 2.0f * (float)xx.y;

    float pn0 = sgn0, pn1 = sgn1;
    int nz0 = 0, nz1 = 0;
#pragma unroll
    for (int k = 0; k < 6; k++) {
        float tk = tanhf(v[k]);
        bool z = (tk == 0.0f);
        nz0 += (int)z;
        pn0 *= z ? 1.0f : tk;
    }
#pragma unroll
    for (int k = 6; k < 12; k++) {
        float tk = tanhf(v[k]);
        bool z = (tk == 0.0f);
        nz1 += (int)z;
        pn1 *= z ? 1.0f : tk;
    }

    float4 out;
    out.x = pn0; out.y = (float)nz0;
    out.z = pn1; out.w = (float)nz1;
    *(float4*)&g_pn_nz[2 * t] = out;
}

// ---------------------------------------------------------------------------
// per-edge factor->variable message reconstructed on the variable side:
// t_self = tanhf(Hsx_self) (bit-identical recompute), aggregate gathered.
// atanh via 0.5*log((1+y)/(1-y)) (abs err ~1e-7; +-inf preserved at y=+-1).
// ---------------------------------------------------------------------------
__device__ __forceinline__ float edge_msg(float hsx, float2 agg)
{
    float ts = tanhf(hsx);
    int nz = (int)agg.y;
    float r;
    if (nz == 0) {
        float y = __fdividef(agg.x, ts);
        r = 0.5f * __logf(__fdividef(1.0f + y, 1.0f - y));
    } else if (nz == 1) {
        if (ts == 0.0f) {
            float y = agg.x;
            r = 0.5f * __logf(__fdividef(1.0f + y, 1.0f - y));
        } else {
            r = 0.0f;
        }
    } else {
        r = 0.0f;
    }
    return r;
}

__device__ __forceinline__ float belief(float h0, float h1, float h2)
{
    float s = (h0 + h1) + h2;
    float d = tanhf(s);
    if (isnan(d)) {
        bool c0 = isinf(h0), c1 = isinf(h1), c2 = isinf(h2);
        if (c0 | c1 | c2) {
            float s2 = (c0 ? 0.0f : h0) + (c1 ? 0.0f : h1) + (c2 ? 0.0f : h2);
            d = tanhf(s2);
        }
    }
    return d;
}

// ---------------------------------------------------------------------------
// Kernel 3: output beliefs. 2 variables per thread.
// Contiguous: g_msg (float2x3), perm (int2x3), output (float4).
// Random: 6 x 8B gathers from the 16MB L2-resident aggregate array.
// ---------------------------------------------------------------------------
__global__ void __launch_bounds__(256)
output_kernel(const int* __restrict__ perm,
              float4* __restrict__ Mout,
              int n_pair)   // n_vars / 2
{
    int t = blockIdx.x * blockDim.x + threadIdx.x;
    if (t >= n_pair) return;

    // 2 variables -> 6 edges
    const float2* msg2 = (const float2*)(g_msg + 6 * t);
    float2 ha = msg2[0], hb = msg2[1], hc = msg2[2];

    const int2* pp = (const int2*)(perm + 6 * t);
    int2 e0 = __ldcs(pp + 0);
    int2 e1 = __ldcs(pp + 1);
    int2 e2 = __ldcs(pp + 2);

    // factor ids (perm value = factor-side slot 6a+k)
    int f0 = e0.x / 6, f1 = e0.y / 6, f2 = e1.x / 6;
    int f3 = e1.y / 6, f4 = e2.x / 6, f5 = e2.y / 6;

    // issue all 6 aggregate gathers back-to-back (8B each, L2-resident)
    float2 g0 = __ldg(&g_pn_nz[f0]);
    float2 g1 = __ldg(&g_pn_nz[f1]);
    float2 g2 = __ldg(&g_pn_nz[f2]);
    float2 g3 = __ldg(&g_pn_nz[f3]);
    float2 g4 = __ldg(&g_pn_nz[f4]);
    float2 g5 = __ldg(&g_pn_nz[f5]);

    float m0 = edge_msg(ha.x, g0);
    float m1 = edge_msg(ha.y, g1);
    float m2 = edge_msg(hb.x, g2);
    float m3 = edge_msg(hb.y, g3);
    float m4 = edge_msg(hc.x, g4);
    float m5 = edge_msg(hc.y, g5);

    float d0 = belief(m0, m1, m2);
    float d1 = belief(m3, m4, m5);

    float4 o;
    o.x = 0.5f + 0.5f * d0;  o.y = 0.5f - 0.5f * d0;
    o.z = 0.5f + 0.5f * d1;  o.w = 0.5f - 0.5f * d1;
    Mout[t] = o;
}

// ---------------------------------------------------------------------------
// Launch. Inputs: ps[N,2] f32, Min[N,2] f32, Hxs_prev[N,3] f32, x[K,1] i32,
// perm[E] i32, inv_perm[E] i32. Output: M_out[N,2] f32.
// ---------------------------------------------------------------------------
extern "C" void kernel_launch(void* const* d_in, const int* in_sizes, int n_in,
                              void* d_out, int out_size)
{
    const float2* ps       = (const float2*)d_in[0];
    const float2* Min      = (const float2*)d_in[1];
    const float*  Hxs_prev = (const float*)d_in[2];
    const int*    x        = (const int*)d_in[3];
    const int*    perm     = (const int*)d_in[4];
    const int*    inv_perm = (const int*)d_in[5];

    int n_vars = in_sizes[0] / 2;   // 4,000,000
    int n_fac  = in_sizes[3];       // 2,000,000
    int n_half = n_fac / 2;         // 1,000,000
    int n_pair = n_vars / 2;        // 2,000,000

    const int T = 256;
    var_update_kernel<<<(n_vars + T - 1) / T, T>>>(ps, Min, Hxs_prev, n_vars);
    fac_aggregate_kernel<<<(n_half + T - 1) / T, T>>>(inv_perm, x, n_half);
    output_kernel<<<(n_pair + T - 1) / T, T>>>(perm, (float4*)d_out, n_pair);
}

// round 6
// speedup vs baseline: 1.7192x; 1.0014x over previous
#include <cuda_runtime.h>
#include <math.h>

// Problem constants (fixed by the reference)
#define NVAR 4000000
#define KFAC 2000000
#define DV 3
#define DC 6
#define EDGES (NVAR * DV)   // 12,000,000

// Scratch (static; allocation-free rule).
// g_t:     t = tanh(Hsx) per edge, variable-side order (48MB). Downstream
//          only ever needs tanh(Hsx), never Hsx itself.
// g_pn_nz: per-factor aggregate {signed tanh-product pn, zero-count nz} (16MB).
__device__ float  g_t[EDGES];
__device__ float2 g_pn_nz[KFAC];

// ---------------------------------------------------------------------------
// Kernel 1: variable -> factor update, fused with tanh. One thread/variable.
// ---------------------------------------------------------------------------
__global__ void __launch_bounds__(256)
var_update_kernel(const float2* __restrict__ ps,
                  const float2* __restrict__ Min,
                  const float*  __restrict__ Hxs_prev,
                  int n_vars)
{
    int n = blockIdx.x * blockDim.x + threadIdx.x;
    if (n >= n_vars) return;

    float2 m = Min[n];
    float2 p = ps[n];
    float prior = 0.5f * (__logf(m.x) - __logf(m.y))
                + 0.5f * (__logf(p.x) - __logf(p.y));

    float h0 = Hxs_prev[3 * n + 0];
    float h1 = Hxs_prev[3 * n + 1];
    float h2 = Hxs_prev[3 * n + 2];

    bool i0 = isinf(h0), i1 = isinf(h1), i2 = isinf(h2);
    int sure = (int)i0 + (int)i1 + (int)i2;

    float o0, o1, o2;
    if (sure == 0) {
        float ll = (h0 + h1) + h2;
        o0 = prior + ll - h0;
        o1 = prior + ll - h1;
        o2 = prior + ll - h2;
    } else {
        float ll = (i0 ? 0.0f : h0) + (i1 ? 0.0f : h1) + (i2 ? 0.0f : h2);
        float ss = (i0 ? h0 : 0.0f) + (i1 ? h1 : 0.0f) + (i2 ? h2 : 0.0f);
        if (sure == 1) {
            float pl = prior + ll;
            o0 = i0 ? pl : ss;
            o1 = i1 ? pl : ss;
            o2 = i2 ? pl : ss;
        } else {
            float v = isnan(ss) ? 0.0f : (prior + ss);
            o0 = v; o1 = v; o2 = v;
        }
    }
    // store tanh(Hsx): tanh(+-inf)=+-1, tanh(nan)=nan -> semantics preserved
    g_t[3 * n + 0] = tanhf(o0);
    g_t[3 * n + 1] = tanhf(o1);
    g_t[3 * n + 2] = tanhf(o2);
}

// ---------------------------------------------------------------------------
// Kernel 2: factor aggregates. 2 factors per thread. Pure gather+multiply:
// 12 random 4B gathers, contiguous 16B aggregate store.
// pn = sign * prod of nonzero t's; nz = count of t==0.
// ---------------------------------------------------------------------------
__global__ void __launch_bounds__(256)
fac_aggregate_kernel(const int* __restrict__ inv_perm,
                     const int* __restrict__ x,
                     int n_half)   // n_fac / 2
{
    int t = blockIdx.x * blockDim.x + threadIdx.x;
    if (t >= n_half) return;

    const int4* ip4 = (const int4*)(inv_perm + 12 * t);   // 48B-aligned
    int4 a0 = __ldcs(ip4 + 0);
    int4 a1 = __ldcs(ip4 + 1);
    int4 a2 = __ldcs(ip4 + 2);
    int idx[12] = {a0.x, a0.y, a0.z, a0.w,
                   a1.x, a1.y, a1.z, a1.w,
                   a2.x, a2.y, a2.z, a2.w};

    float v[12];
#pragma unroll
    for (int k = 0; k < 12; k++)
        v[k] = __ldcg(&g_t[idx[k]]);

    int2 xx = __ldcs((const int2*)(x + 2 * t));
    float pn0 = 1.0f - 2.0f * (float)xx.x;
    float pn1 = 1.0f - 2.0f * (float)xx.y;

    int nz0 = 0, nz1 = 0;
#pragma unroll
    for (int k = 0; k < 6; k++) {
        bool z = (v[k] == 0.0f);
        nz0 += (int)z;
        pn0 *= z ? 1.0f : v[k];
    }
#pragma unroll
    for (int k = 6; k < 12; k++) {
        bool z = (v[k] == 0.0f);
        nz1 += (int)z;
        pn1 *= z ? 1.0f : v[k];
    }

    float4 out;
    out.x = pn0; out.y = (float)nz0;
    out.z = pn1; out.w = (float)nz1;
    *(float4*)&g_pn_nz[2 * t] = out;
}

// ---------------------------------------------------------------------------
// per-edge message from self-tanh + factor aggregate.
// atanh(pn/t) = 0.5*log((t+pn)/(t-pn)):
//   t>0 or t<0: ratio invariant under sign of t  -> correct sign
//   |pn|==|t|:  ratio is +inf or 0 -> log -> +-inf  (matches arctanh(+-1))
//   |pn| > |t|: ratio negative -> log -> nan        (matches arctanh(|y|>1))
//   pn nan:     propagates nan
// ---------------------------------------------------------------------------
__device__ __forceinline__ float edge_msg(float ts, float2 agg)
{
    int nz = (int)agg.y;
    float r = 0.0f;
    if (nz == 0) {
        r = 0.5f * __logf(__fdividef(ts + agg.x, ts - agg.x));
    } else if (nz == 1) {
        if (ts == 0.0f)
            r = 0.5f * __logf(__fdividef(1.0f + agg.x, 1.0f - agg.x));
    }
    return r;
}

__device__ __forceinline__ float belief(float h0, float h1, float h2)
{
    float s = (h0 + h1) + h2;
    float d = tanhf(s);
    if (isnan(d)) {
        bool c0 = isinf(h0), c1 = isinf(h1), c2 = isinf(h2);
        if (c0 | c1 | c2) {
            float s2 = (c0 ? 0.0f : h0) + (c1 ? 0.0f : h1) + (c2 ? 0.0f : h2);
            d = tanhf(s2);
        }
    }
    return d;
}

// ---------------------------------------------------------------------------
// Kernel 3: output beliefs. One thread per variable.
// Contiguous: g_t (3x4B), perm (3x4B), output (float2).
// Random: 3 x 8B gathers from the 16MB L2-resident aggregate array,
// issued back-to-back before any math.
// ---------------------------------------------------------------------------
__global__ void __launch_bounds__(256)
output_kernel(const int* __restrict__ perm,
              float2* __restrict__ Mout,
              int n_vars)
{
    int n = blockIdx.x * blockDim.x + threadIdx.x;
    if (n >= n_vars) return;

    int e0 = __ldcs(&perm[3 * n + 0]);
    int e1 = __ldcs(&perm[3 * n + 1]);
    int e2 = __ldcs(&perm[3 * n + 2]);

    float t0 = g_t[3 * n + 0];
    float t1 = g_t[3 * n + 1];
    float t2 = g_t[3 * n + 2];

    // factor ids (perm value = factor-side slot 6a+k)
    float2 ga = __ldg(&g_pn_nz[e0 / 6]);
    float2 gb = __ldg(&g_pn_nz[e1 / 6]);
    float2 gc = __ldg(&g_pn_nz[e2 / 6]);

    float m0 = edge_msg(t0, ga);
    float m1 = edge_msg(t1, gb);
    float m2 = edge_msg(t2, gc);

    float d = belief(m0, m1, m2);

    float2 o;
    o.x = 0.5f + 0.5f * d;
    o.y = 0.5f - 0.5f * d;
    Mout[n] = o;
}

// ---------------------------------------------------------------------------
// Launch. Inputs: ps[N,2] f32, Min[N,2] f32, Hxs_prev[N,3] f32, x[K,1] i32,
// perm[E] i32, inv_perm[E] i32. Output: M_out[N,2] f32.
// ---------------------------------------------------------------------------
extern "C" void kernel_launch(void* const* d_in, const int* in_sizes, int n_in,
                              void* d_out, int out_size)
{
    const float2* ps       = (const float2*)d_in[0];
    const float2* Min      = (const float2*)d_in[1];
    const float*  Hxs_prev = (const float*)d_in[2];
    const int*    x        = (const int*)d_in[3];
    const int*    perm     = (const int*)d_in[4];
    const int*    inv_perm = (const int*)d_in[5];

    int n_vars = in_sizes[0] / 2;   // 4,000,000
    int n_fac  = in_sizes[3];       // 2,000,000
    int n_half = n_fac / 2;         // 1,000,000

    const int T = 256;
    var_update_kernel<<<(n_vars + T - 1) / T, T>>>(ps, Min, Hxs_prev, n_vars);
    fac_aggregate_kernel<<<(n_half + T - 1) / T, T>>>(inv_perm, x, n_half);
    output_kernel<<<(n_vars + T - 1) / T, T>>>(perm, (float2*)d_out, n_vars);
}